// round 1
// baseline (speedup 1.0000x reference)
#include <cuda_runtime.h>
#include <cuda_bf16.h>
#include <cstddef>

// ---------------------------------------------------------------------------
// Problem constants
// ---------------------------------------------------------------------------
#define BATCH      8
#define SEQ_LEN    1124
#define EMBED      1024
#define NHEADS     16
#define HEADDIM    64
#define MLP_HID    4096
#define NPATCH     1024
#define NQUERY     100
#define TOKENS     (BATCH * SEQ_LEN)          // 8992
#define SCALE_F    0.125f                     // 64^-0.5
#define LN_EPS     1e-6f

// ---------------------------------------------------------------------------
// Scratch (static __device__ arrays; no allocation allowed)
// ---------------------------------------------------------------------------
__device__ float g_xn  [(size_t)TOKENS * EMBED];    // LN1 out, reused as LN2 out
__device__ float g_qkv [(size_t)TOKENS * 3 * EMBED];
__device__ float g_attn[(size_t)TOKENS * EMBED];
__device__ float g_x1  [(size_t)TOKENS * EMBED];    // x + attn proj (residual 1)
__device__ float g_mid [(size_t)TOKENS * MLP_HID];  // gelu(fc1)

// ---------------------------------------------------------------------------
// LayerNorm: one block per token row (1024 elems, 256 threads x float4)
// ---------------------------------------------------------------------------
__global__ void __launch_bounds__(256)
ln_kernel(const float* __restrict__ x, const float* __restrict__ g,
          const float* __restrict__ b, float* __restrict__ y)
{
    const int row = blockIdx.x;
    const int t   = threadIdx.x;
    const float* xr = x + (size_t)row * EMBED;

    float4 v = *(const float4*)(xr + t * 4);
    float s  = v.x + v.y + v.z + v.w;
    float sq = v.x*v.x + v.y*v.y + v.z*v.z + v.w*v.w;

    #pragma unroll
    for (int off = 16; off > 0; off >>= 1) {
        s  += __shfl_xor_sync(0xffffffffu, s,  off);
        sq += __shfl_xor_sync(0xffffffffu, sq, off);
    }
    __shared__ float red_s[8], red_q[8];
    const int wid = t >> 5, lane = t & 31;
    if (lane == 0) { red_s[wid] = s; red_q[wid] = sq; }
    __syncthreads();
    float ts = 0.f, tq = 0.f;
    #pragma unroll
    for (int w = 0; w < 8; w++) { ts += red_s[w]; tq += red_q[w]; }

    const float mean = ts * (1.0f / EMBED);
    const float var  = tq * (1.0f / EMBED) - mean * mean;
    const float inv  = rsqrtf(var + LN_EPS);

    float4 gg = *(const float4*)(g + t * 4);
    float4 bb = *(const float4*)(b + t * 4);
    float4 o;
    o.x = (v.x - mean) * inv * gg.x + bb.x;
    o.y = (v.y - mean) * inv * gg.y + bb.y;
    o.z = (v.z - mean) * inv * gg.z + bb.z;
    o.w = (v.w - mean) * inv * gg.w + bb.w;
    *(float4*)(y + (size_t)row * EMBED + t * 4) = o;
}

// ---------------------------------------------------------------------------
// SGEMM: C[M,N] = A[M,K] @ B[K,N] (+bias) (+GELU) (+residual)
// 128x128 tile, BK=16, 256 threads, 8x8 per thread, reg-prefetch pipeline.
// N % 128 == 0, K % 16 == 0 guaranteed; M ragged (bounds-checked).
// ---------------------------------------------------------------------------
#define BM 128
#define BN 128
#define BK 16

__global__ void __launch_bounds__(256)
gemm_kernel(const float* __restrict__ A, const float* __restrict__ B,
            const float* __restrict__ bias, const float* __restrict__ res,
            float* __restrict__ C, int M, int N, int K, int doGelu)
{
    __shared__ float As[BK][BM + 4];   // k-major, transposed A tile
    __shared__ float Bs[BK][BN];

    const int t     = threadIdx.x;
    const int gRow0 = blockIdx.y * BM;
    const int gCol0 = blockIdx.x * BN;
    const int rowBase = (t >> 4) << 3;     // 0..120
    const int colBase = (t & 15) << 3;     // 0..120

    // A-load mapping (2 float4 per thread along K)
    const int arow0 = t >> 2;              // 0..63
    const int akq   = t & 3;               // 0..3  (k-quad)
    const int arow1 = arow0 + 64;
    // B-load mapping (2 float4 per thread along N)
    const int bkr0  = t >> 5;              // 0..7
    const int bnq   = t & 31;              // 0..31
    const int bkr1  = bkr0 + 8;

    float acc[8][8];
    #pragma unroll
    for (int i = 0; i < 8; i++)
        #pragma unroll
        for (int j = 0; j < 8; j++) acc[i][j] = 0.f;

    const float4 z4 = make_float4(0.f, 0.f, 0.f, 0.f);
    const int nk = K / BK;

    // prologue: load tile 0
    float4 pa0, pa1, pb0, pb1;
    {
        const int k0 = 0;
        const int r0 = gRow0 + arow0, r1 = gRow0 + arow1;
        pa0 = (r0 < M) ? *(const float4*)(A + (size_t)r0 * K + k0 + akq * 4) : z4;
        pa1 = (r1 < M) ? *(const float4*)(A + (size_t)r1 * K + k0 + akq * 4) : z4;
        pb0 = *(const float4*)(B + (size_t)(k0 + bkr0) * N + gCol0 + bnq * 4);
        pb1 = *(const float4*)(B + (size_t)(k0 + bkr1) * N + gCol0 + bnq * 4);
    }
    {
        As[akq*4+0][arow0] = pa0.x; As[akq*4+1][arow0] = pa0.y;
        As[akq*4+2][arow0] = pa0.z; As[akq*4+3][arow0] = pa0.w;
        As[akq*4+0][arow1] = pa1.x; As[akq*4+1][arow1] = pa1.y;
        As[akq*4+2][arow1] = pa1.z; As[akq*4+3][arow1] = pa1.w;
        *(float4*)&Bs[bkr0][bnq*4] = pb0;
        *(float4*)&Bs[bkr1][bnq*4] = pb1;
    }
    __syncthreads();

    for (int kt = 0; kt < nk; kt++) {
        const bool has = (kt + 1 < nk);
        if (has) {
            const int k0 = (kt + 1) * BK;
            const int r0 = gRow0 + arow0, r1 = gRow0 + arow1;
            pa0 = (r0 < M) ? *(const float4*)(A + (size_t)r0 * K + k0 + akq * 4) : z4;
            pa1 = (r1 < M) ? *(const float4*)(A + (size_t)r1 * K + k0 + akq * 4) : z4;
            pb0 = *(const float4*)(B + (size_t)(k0 + bkr0) * N + gCol0 + bnq * 4);
            pb1 = *(const float4*)(B + (size_t)(k0 + bkr1) * N + gCol0 + bnq * 4);
        }

        #pragma unroll
        for (int kk = 0; kk < BK; kk++) {
            float4 a0 = *(const float4*)&As[kk][rowBase];
            float4 a1 = *(const float4*)&As[kk][rowBase + 4];
            float4 b0 = *(const float4*)&Bs[kk][colBase];
            float4 b1 = *(const float4*)&Bs[kk][colBase + 4];
            float af[8] = {a0.x,a0.y,a0.z,a0.w,a1.x,a1.y,a1.z,a1.w};
            float bf[8] = {b0.x,b0.y,b0.z,b0.w,b1.x,b1.y,b1.z,b1.w};
            #pragma unroll
            for (int i = 0; i < 8; i++)
                #pragma unroll
                for (int j = 0; j < 8; j++)
                    acc[i][j] = fmaf(af[i], bf[j], acc[i][j]);
        }
        __syncthreads();
        if (has) {
            As[akq*4+0][arow0] = pa0.x; As[akq*4+1][arow0] = pa0.y;
            As[akq*4+2][arow0] = pa0.z; As[akq*4+3][arow0] = pa0.w;
            As[akq*4+0][arow1] = pa1.x; As[akq*4+1][arow1] = pa1.y;
            As[akq*4+2][arow1] = pa1.z; As[akq*4+3][arow1] = pa1.w;
            *(float4*)&Bs[bkr0][bnq*4] = pb0;
            *(float4*)&Bs[bkr1][bnq*4] = pb1;
            __syncthreads();
        }
    }

    // epilogue
    #pragma unroll
    for (int i = 0; i < 8; i++) {
        const int r = gRow0 + rowBase + i;
        if (r >= M) continue;
        #pragma unroll
        for (int jv = 0; jv < 2; jv++) {
            const int cb = gCol0 + colBase + jv * 4;
            float v[4];
            #pragma unroll
            for (int u = 0; u < 4; u++) v[u] = acc[i][jv * 4 + u];
            if (bias) {
                float4 bv = *(const float4*)(bias + cb);
                v[0] += bv.x; v[1] += bv.y; v[2] += bv.z; v[3] += bv.w;
            }
            if (doGelu) {
                #pragma unroll
                for (int u = 0; u < 4; u++)
                    v[u] = 0.5f * v[u] * (1.0f + erff(v[u] * 0.70710678118654752f));
            }
            if (res) {
                float4 rv = *(const float4*)(res + (size_t)r * N + cb);
                v[0] += rv.x; v[1] += rv.y; v[2] += rv.z; v[3] += rv.w;
            }
            float4 o = make_float4(v[0], v[1], v[2], v[3]);
            *(float4*)(C + (size_t)r * N + cb) = o;
        }
    }
}

// ---------------------------------------------------------------------------
// Flash-style attention, fp32. One block = (one (b,h), 64 q-rows).
// 256 threads: t = rg*16 + c;  rg in [0,16) -> rows {rg, rg+16, rg+32, rg+48}
//                               c  in [0,16) -> keys {c, c+16, c+32, c+48} (scores)
//                                              dims {4c..4c+3}            (PV / out)
// Dynamic smem: Qs[64][68] | KVs[64][68] (K then V) | Ps[64][68]
// ---------------------------------------------------------------------------
#define LDSA 68
#define ATTN_SMEM (3 * 64 * LDSA * 4)

__global__ void __launch_bounds__(256)
attn_kernel(const float* __restrict__ qkv, const float* __restrict__ mask,
            float* __restrict__ out)
{
    extern __shared__ float sm[];
    float* Qs  = sm;
    float* KVs = sm + 64 * LDSA;
    float* Ps  = sm + 2 * 64 * LDSA;

    const int t  = threadIdx.x;
    const int qt = blockIdx.x;            // 0..17
    const int bh = blockIdx.y;            // 0..127
    const int b  = bh >> 4;
    const int h  = bh & 15;
    const int qBase = qt * 64;

    const float* qptr = qkv + (size_t)b * SEQ_LEN * 3072 + h * HEADDIM;
    const float* kptr = qptr + EMBED;
    const float* vptr = qptr + 2 * EMBED;

    // load Q tile (64 rows x 64 dims)
    for (int slot = t; slot < 64 * 16; slot += 256) {
        const int row = slot >> 4, dq = slot & 15;
        const int gq = qBase + row;
        float4 v = make_float4(0.f, 0.f, 0.f, 0.f);
        if (gq < SEQ_LEN) v = *(const float4*)(qptr + (size_t)gq * 3072 + dq * 4);
        *(float4*)&Qs[row * LDSA + dq * 4] = v;
    }

    const int rg = t >> 4;
    const int c  = t & 15;

    float m[4], l[4];
    float4 o[4];
    #pragma unroll
    for (int i = 0; i < 4; i++) {
        m[i] = -1e30f; l[i] = 0.f; o[i] = make_float4(0.f, 0.f, 0.f, 0.f);
    }
    __syncthreads();

    const int nkt = (SEQ_LEN + 63) / 64;   // 18
    for (int kt = 0; kt < nkt; kt++) {
        const int kBase = kt * 64;

        // load K tile
        for (int slot = t; slot < 64 * 16; slot += 256) {
            const int row = slot >> 4, dq = slot & 15;
            const int gk = kBase + row;
            float4 v = make_float4(0.f, 0.f, 0.f, 0.f);
            if (gk < SEQ_LEN) v = *(const float4*)(kptr + (size_t)gk * 3072 + dq * 4);
            *(float4*)&KVs[row * LDSA + dq * 4] = v;
        }
        __syncthreads();

        // scores: s[i][j] = Q[rg+16i] . K[c+16j]
        float s[4][4];
        #pragma unroll
        for (int i = 0; i < 4; i++)
            #pragma unroll
            for (int j = 0; j < 4; j++) s[i][j] = 0.f;

        #pragma unroll
        for (int d4 = 0; d4 < 16; d4++) {
            float4 qv[4], kv[4];
            #pragma unroll
            for (int i = 0; i < 4; i++)
                qv[i] = *(const float4*)&Qs[(rg + 16 * i) * LDSA + d4 * 4];
            #pragma unroll
            for (int j = 0; j < 4; j++)
                kv[j] = *(const float4*)&KVs[(c + 16 * j) * LDSA + d4 * 4];
            #pragma unroll
            for (int i = 0; i < 4; i++)
                #pragma unroll
                for (int j = 0; j < 4; j++) {
                    s[i][j] = fmaf(qv[i].x, kv[j].x, s[i][j]);
                    s[i][j] = fmaf(qv[i].y, kv[j].y, s[i][j]);
                    s[i][j] = fmaf(qv[i].z, kv[j].z, s[i][j]);
                    s[i][j] = fmaf(qv[i].w, kv[j].w, s[i][j]);
                }
        }

        // scale + validity + mask
        #pragma unroll
        for (int i = 0; i < 4; i++) {
            const int gq = qBase + rg + 16 * i;
            #pragma unroll
            for (int j = 0; j < 4; j++) {
                const int gk = kBase + c + 16 * j;
                float sv = s[i][j] * SCALE_F;
                if (gk >= SEQ_LEN) {
                    sv = -1e30f;
                } else if (gq >= NPATCH && gq < SEQ_LEN && gk < NPATCH) {
                    const float mv =
                        mask[((size_t)b * NQUERY + (gq - NPATCH)) * NPATCH + gk];
                    if (!(mv > 0.5f)) sv = -1e9f;
                }
                s[i][j] = sv;
            }
        }

        // online softmax update (row reductions across the 16-lane group)
        #pragma unroll
        for (int i = 0; i < 4; i++) {
            float mx = fmaxf(fmaxf(s[i][0], s[i][1]), fmaxf(s[i][2], s[i][3]));
            #pragma unroll
            for (int off = 1; off < 16; off <<= 1)
                mx = fmaxf(mx, __shfl_xor_sync(0xffffffffu, mx, off));
            const float nm    = fmaxf(m[i], mx);
            const float alpha = __expf(m[i] - nm);
            m[i] = nm;
            float rs = 0.f;
            #pragma unroll
            for (int j = 0; j < 4; j++) {
                const float p = __expf(s[i][j] - nm);
                rs += p;
                Ps[(rg + 16 * i) * LDSA + c + 16 * j] = p;
            }
            #pragma unroll
            for (int off = 1; off < 16; off <<= 1)
                rs += __shfl_xor_sync(0xffffffffu, rs, off);
            l[i] = l[i] * alpha + rs;
            o[i].x *= alpha; o[i].y *= alpha; o[i].z *= alpha; o[i].w *= alpha;
        }
        __syncthreads();   // Ps written; K reads done

        // load V tile (overwrites KVs)
        for (int slot = t; slot < 64 * 16; slot += 256) {
            const int row = slot >> 4, dq = slot & 15;
            const int gk = kBase + row;
            float4 v = make_float4(0.f, 0.f, 0.f, 0.f);
            if (gk < SEQ_LEN) v = *(const float4*)(vptr + (size_t)gk * 3072 + dq * 4);
            *(float4*)&KVs[row * LDSA + dq * 4] = v;
        }
        __syncthreads();

        // O[rg+16i][4c..4c+3] += sum_k Ps[row][k] * V[k][4c..4c+3]
        #pragma unroll 4
        for (int k = 0; k < 64; k++) {
            const float4 vv = *(const float4*)&KVs[k * LDSA + c * 4];
            #pragma unroll
            for (int i = 0; i < 4; i++) {
                const float p = Ps[(rg + 16 * i) * LDSA + k];
                o[i].x = fmaf(p, vv.x, o[i].x);
                o[i].y = fmaf(p, vv.y, o[i].y);
                o[i].z = fmaf(p, vv.z, o[i].z);
                o[i].w = fmaf(p, vv.w, o[i].w);
            }
        }
        __syncthreads();   // before next K load / Ps rewrite
    }

    // write output: out[b, gq, h*64 + 4c .. +3]
    #pragma unroll
    for (int i = 0; i < 4; i++) {
        const int gq = qBase + rg + 16 * i;
        if (gq < SEQ_LEN) {
            const float inv = 1.0f / l[i];
            float4 r = make_float4(o[i].x * inv, o[i].y * inv,
                                   o[i].z * inv, o[i].w * inv);
            *(float4*)(out + ((size_t)(b * SEQ_LEN + gq)) * EMBED
                           + h * HEADDIM + c * 4) = r;
        }
    }
}

// ---------------------------------------------------------------------------
// Launch
// ---------------------------------------------------------------------------
extern "C" void kernel_launch(void* const* d_in, const int* in_sizes, int n_in,
                              void* d_out, int out_size)
{
    const float* x      = (const float*)d_in[0];
    const float* mask   = (const float*)d_in[1];
    const float* qkv_w  = (const float*)d_in[2];
    const float* proj_w = (const float*)d_in[3];
    const float* proj_b = (const float*)d_in[4];
    const float* ln1_g  = (const float*)d_in[5];
    const float* ln1_b  = (const float*)d_in[6];
    const float* ln2_g  = (const float*)d_in[7];
    const float* ln2_b  = (const float*)d_in[8];
    const float* fc1_w  = (const float*)d_in[9];
    const float* fc1_b  = (const float*)d_in[10];
    const float* fc2_w  = (const float*)d_in[11];
    const float* fc2_b  = (const float*)d_in[12];
    float* out = (float*)d_out;

    float *p_xn, *p_qkv, *p_attn, *p_x1, *p_mid;
    cudaGetSymbolAddress((void**)&p_xn,   g_xn);
    cudaGetSymbolAddress((void**)&p_qkv,  g_qkv);
    cudaGetSymbolAddress((void**)&p_attn, g_attn);
    cudaGetSymbolAddress((void**)&p_x1,   g_x1);
    cudaGetSymbolAddress((void**)&p_mid,  g_mid);

    cudaFuncSetAttribute(attn_kernel,
                         cudaFuncAttributeMaxDynamicSharedMemorySize, ATTN_SMEM);

    const int M = TOKENS;                        // 8992
    const dim3 blk(256);
    const int mblk = (M + BM - 1) / BM;          // 71

    // 1) LN1
    ln_kernel<<<M, blk>>>(x, ln1_g, ln1_b, p_xn);
    // 2) qkv = xn @ qkv_w
    gemm_kernel<<<dim3(3 * EMBED / BN, mblk), blk>>>(
        p_xn, qkv_w, nullptr, nullptr, p_qkv, M, 3 * EMBED, EMBED, 0);
    // 3) attention
    attn_kernel<<<dim3(18, BATCH * NHEADS), blk, ATTN_SMEM>>>(p_qkv, mask, p_attn);
    // 4) x1 = attn @ proj_w + proj_b + x
    gemm_kernel<<<dim3(EMBED / BN, mblk), blk>>>(
        p_attn, proj_w, proj_b, x, p_x1, M, EMBED, EMBED, 0);
    // 5) LN2 (reuse xn buffer)
    ln_kernel<<<M, blk>>>(p_x1, ln2_g, ln2_b, p_xn);
    // 6) mid = gelu(xn @ fc1_w + fc1_b)
    gemm_kernel<<<dim3(MLP_HID / BN, mblk), blk>>>(
        p_xn, fc1_w, fc1_b, nullptr, p_mid, M, MLP_HID, EMBED, 1);
    // 7) out = mid @ fc2_w + fc2_b + x1
    gemm_kernel<<<dim3(EMBED / BN, mblk), blk>>>(
        p_mid, fc2_w, fc2_b, p_x1, out, M, EMBED, MLP_HID, 0);
}

// round 4
// speedup vs baseline: 2.1914x; 2.1914x over previous
#include <cuda_runtime.h>
#include <cuda_bf16.h>
#include <cstdint>
#include <cstddef>

// ---------------------------------------------------------------------------
// Problem constants
// ---------------------------------------------------------------------------
#define BATCH      8
#define SEQ_LEN    1124
#define EMBED      1024
#define NHEADS     16
#define HEADDIM    64
#define MLP_HID    4096
#define NPATCH     1024
#define NQUERY     100
#define TOKENS     (BATCH * SEQ_LEN)          // 8992
#define SCALE_F    0.125f                     // 64^-0.5
#define LN_EPS     1e-6f

// ---------------------------------------------------------------------------
// Scratch (static __device__ arrays; no allocation allowed)
// ---------------------------------------------------------------------------
__device__ float g_xn  [(size_t)TOKENS * EMBED];    // LN1 out, reused as LN2 out
__device__ float g_qkv [(size_t)TOKENS * 3 * EMBED];
__device__ float g_attn[(size_t)TOKENS * EMBED];
__device__ float g_x1  [(size_t)TOKENS * EMBED];    // x + attn proj (residual 1)
__device__ float g_mid [(size_t)TOKENS * MLP_HID];  // gelu(fc1)

// ---------------------------------------------------------------------------
// PTX helpers
// ---------------------------------------------------------------------------
__device__ __forceinline__ uint32_t f2tf32(float f) {
    uint32_t u;
    asm("cvt.rna.tf32.f32 %0, %1;" : "=r"(u) : "f"(f));
    return u;
}

__device__ __forceinline__ void mma_tf32(float* d, const uint32_t* a,
                                         const uint32_t* b) {
    asm volatile(
        "mma.sync.aligned.m16n8k8.row.col.f32.tf32.tf32.f32 "
        "{%0,%1,%2,%3}, {%4,%5,%6,%7}, {%8,%9}, {%0,%1,%2,%3};\n"
        : "+f"(d[0]), "+f"(d[1]), "+f"(d[2]), "+f"(d[3])
        : "r"(a[0]), "r"(a[1]), "r"(a[2]), "r"(a[3]),
          "r"(b[0]), "r"(b[1]));
}

// ---------------------------------------------------------------------------
// LayerNorm: one block per token row (1024 elems, 256 threads x float4)
// ---------------------------------------------------------------------------
__global__ void __launch_bounds__(256)
ln_kernel(const float* __restrict__ x, const float* __restrict__ g,
          const float* __restrict__ b, float* __restrict__ y)
{
    const int row = blockIdx.x;
    const int t   = threadIdx.x;
    const float* xr = x + (size_t)row * EMBED;

    float4 v = *(const float4*)(xr + t * 4);
    float s  = v.x + v.y + v.z + v.w;
    float sq = v.x*v.x + v.y*v.y + v.z*v.z + v.w*v.w;

    #pragma unroll
    for (int off = 16; off > 0; off >>= 1) {
        s  += __shfl_xor_sync(0xffffffffu, s,  off);
        sq += __shfl_xor_sync(0xffffffffu, sq, off);
    }
    __shared__ float red_s[8], red_q[8];
    const int wid = t >> 5, lane = t & 31;
    if (lane == 0) { red_s[wid] = s; red_q[wid] = sq; }
    __syncthreads();
    float ts = 0.f, tq = 0.f;
    #pragma unroll
    for (int w = 0; w < 8; w++) { ts += red_s[w]; tq += red_q[w]; }

    const float mean = ts * (1.0f / EMBED);
    const float var  = tq * (1.0f / EMBED) - mean * mean;
    const float inv  = rsqrtf(var + LN_EPS);

    float4 gg = *(const float4*)(g + t * 4);
    float4 bb = *(const float4*)(b + t * 4);
    float4 o;
    o.x = (v.x - mean) * inv * gg.x + bb.x;
    o.y = (v.y - mean) * inv * gg.y + bb.y;
    o.z = (v.z - mean) * inv * gg.z + bb.z;
    o.w = (v.w - mean) * inv * gg.w + bb.w;
    *(float4*)(y + (size_t)row * EMBED + t * 4) = o;
}

// ---------------------------------------------------------------------------
// TF32 tensor-core GEMM: C[M,N] = A[M,K] @ B[K,N] (+bias)(+GELU)(+residual)
// 128x128x32 CTA tile, 256 threads (8 warps, 4x2), warp tile 32x64.
// mma.sync.m16n8k8 tf32. Register-staged global loads (no cp.async),
// single static smem buffer, two barriers per K-tile (Round-1-proven schedule).
// N % 128 == 0, K % 32 == 0; M ragged (predicated, addresses clamped).
// ---------------------------------------------------------------------------
#define TBM 128
#define TBN 128
#define TBK 32
#define A_STRIDE 36    // TBK + 4 : A stored [m][k]; frag reads conflict-free
#define B_STRIDE 136   // TBN + 8 : B stored [k][n]; frag reads conflict-free

__global__ void __launch_bounds__(256)
gemm_tf32_kernel(const float* __restrict__ A, const float* __restrict__ B,
                 const float* __restrict__ bias, const float* __restrict__ res,
                 float* __restrict__ C, int M, int N, int K, int doGelu)
{
    __shared__ float As[TBM * A_STRIDE];   // 18432 B
    __shared__ float Bs[TBK * B_STRIDE];   // 17408 B

    const int t     = threadIdx.x;
    const int wid   = t >> 5;
    const int lane  = t & 31;
    const int warpM = wid & 3;     // 4 warps along M (32 rows each)
    const int warpN = wid >> 2;    // 2 warps along N (64 cols each)
    const int g     = lane >> 2;   // 0..7
    const int tg    = lane & 3;    // 0..3
    const int gRow0 = blockIdx.y * TBM;
    const int gCol0 = blockIdx.x * TBN;

    // global->smem load mapping (4 float4 each for A and B per thread)
    const int a_r  = t >> 3;            // rows 0..31 (+32 per i)
    const int a_kq = t & 7;             // k-quad 0..7
    const int b_r  = t >> 5;            // k rows 0..7 (+8 per i)
    const int b_nq = t & 31;            // n-quad 0..31

    float acc[2][8][4];
    #pragma unroll
    for (int mi = 0; mi < 2; mi++)
        #pragma unroll
        for (int ni = 0; ni < 8; ni++)
            #pragma unroll
            for (int u = 0; u < 4; u++) acc[mi][ni][u] = 0.f;

    float4 ra[4], rb[4];
    auto fetchTile = [&](int kt) {
        const int k0 = kt * TBK;
        #pragma unroll
        for (int i = 0; i < 4; i++) {
            const int gr  = gRow0 + a_r + i * 32;
            const int grc = gr < M ? gr : (M - 1);   // clamped, always in-bounds
            ra[i] = *(const float4*)(A + (size_t)grc * K + k0 + a_kq * 4);
        }
        #pragma unroll
        for (int i = 0; i < 4; i++) {
            const int r = b_r + i * 8;
            rb[i] = *(const float4*)(B + (size_t)(k0 + r) * N + gCol0 + b_nq * 4);
        }
    };
    auto stageTile = [&]() {
        #pragma unroll
        for (int i = 0; i < 4; i++)
            *(float4*)&As[(a_r + i * 32) * A_STRIDE + a_kq * 4] = ra[i];
        #pragma unroll
        for (int i = 0; i < 4; i++)
            *(float4*)&Bs[(b_r + i * 8) * B_STRIDE + b_nq * 4] = rb[i];
    };

    const int nk = K / TBK;
    fetchTile(0);
    stageTile();
    __syncthreads();

    for (int kt = 0; kt < nk; kt++) {
        if (kt + 1 < nk) fetchTile(kt + 1);   // issue next-tile loads early

        #pragma unroll
        for (int ks = 0; ks < 4; ks++) {
            const int kk = ks * 8;
            uint32_t af[2][4], bf[8][2];
            #pragma unroll
            for (int mi = 0; mi < 2; mi++) {
                const int m0 = warpM * 32 + mi * 16;
                af[mi][0] = f2tf32(As[(m0 + g)     * A_STRIDE + kk + tg]);
                af[mi][1] = f2tf32(As[(m0 + g + 8) * A_STRIDE + kk + tg]);
                af[mi][2] = f2tf32(As[(m0 + g)     * A_STRIDE + kk + tg + 4]);
                af[mi][3] = f2tf32(As[(m0 + g + 8) * A_STRIDE + kk + tg + 4]);
            }
            #pragma unroll
            for (int ni = 0; ni < 8; ni++) {
                const int n0 = warpN * 64 + ni * 8;
                bf[ni][0] = f2tf32(Bs[(kk + tg)     * B_STRIDE + n0 + g]);
                bf[ni][1] = f2tf32(Bs[(kk + tg + 4) * B_STRIDE + n0 + g]);
            }
            #pragma unroll
            for (int mi = 0; mi < 2; mi++)
                #pragma unroll
                for (int ni = 0; ni < 8; ni++)
                    mma_tf32(acc[mi][ni], af[mi], bf[ni]);
        }

        __syncthreads();                      // all reads of this tile done
        if (kt + 1 < nk) {
            stageTile();
            __syncthreads();                  // next tile visible
        }
    }

    // epilogue: C frag layout c0:(g,2tg) c1:(g,2tg+1) c2:(g+8,2tg) c3:(g+8,2tg+1)
    #pragma unroll
    for (int mi = 0; mi < 2; mi++) {
        #pragma unroll
        for (int half = 0; half < 2; half++) {
            const int r = gRow0 + warpM * 32 + mi * 16 + g + half * 8;
            if (r >= M) continue;
            #pragma unroll
            for (int ni = 0; ni < 8; ni++) {
                const int col = gCol0 + warpN * 64 + ni * 8 + tg * 2;
                float v0 = acc[mi][ni][half * 2 + 0];
                float v1 = acc[mi][ni][half * 2 + 1];
                if (bias) { v0 += bias[col]; v1 += bias[col + 1]; }
                if (doGelu) {
                    v0 = 0.5f * v0 * (1.0f + erff(v0 * 0.70710678118654752f));
                    v1 = 0.5f * v1 * (1.0f + erff(v1 * 0.70710678118654752f));
                }
                if (res) {
                    const float2 rv = *(const float2*)(res + (size_t)r * N + col);
                    v0 += rv.x; v1 += rv.y;
                }
                *(float2*)(C + (size_t)r * N + col) = make_float2(v0, v1);
            }
        }
    }
}

// ---------------------------------------------------------------------------
// Flash-style attention, fp32. One block = (one (b,h), 64 q-rows).
// 256 threads: t = rg*16 + c;  rg in [0,16) -> rows {rg, rg+16, rg+32, rg+48}
//                               c  in [0,16) -> keys {c, c+16, c+32, c+48} (scores)
//                                              dims {4c..4c+3}            (PV / out)
// ---------------------------------------------------------------------------
#define LDSA 68
#define ATTN_SMEM (3 * 64 * LDSA * 4)

__global__ void __launch_bounds__(256)
attn_kernel(const float* __restrict__ qkv, const float* __restrict__ mask,
            float* __restrict__ out)
{
    extern __shared__ float sm[];
    float* Qs  = sm;
    float* KVs = sm + 64 * LDSA;
    float* Ps  = sm + 2 * 64 * LDSA;

    const int t  = threadIdx.x;
    const int qt = blockIdx.x;            // 0..17
    const int bh = blockIdx.y;            // 0..127
    const int b  = bh >> 4;
    const int h  = bh & 15;
    const int qBase = qt * 64;

    const float* qptr = qkv + (size_t)b * SEQ_LEN * 3072 + h * HEADDIM;
    const float* kptr = qptr + EMBED;
    const float* vptr = qptr + 2 * EMBED;

    for (int slot = t; slot < 64 * 16; slot += 256) {
        const int row = slot >> 4, dq = slot & 15;
        const int gq = qBase + row;
        float4 v = make_float4(0.f, 0.f, 0.f, 0.f);
        if (gq < SEQ_LEN) v = *(const float4*)(qptr + (size_t)gq * 3072 + dq * 4);
        *(float4*)&Qs[row * LDSA + dq * 4] = v;
    }

    const int rg = t >> 4;
    const int c  = t & 15;

    float m[4], l[4];
    float4 o[4];
    #pragma unroll
    for (int i = 0; i < 4; i++) {
        m[i] = -1e30f; l[i] = 0.f; o[i] = make_float4(0.f, 0.f, 0.f, 0.f);
    }
    __syncthreads();

    const int nkt = (SEQ_LEN + 63) / 64;   // 18
    for (int kt = 0; kt < nkt; kt++) {
        const int kBase = kt * 64;

        for (int slot = t; slot < 64 * 16; slot += 256) {
            const int row = slot >> 4, dq = slot & 15;
            const int gk = kBase + row;
            float4 v = make_float4(0.f, 0.f, 0.f, 0.f);
            if (gk < SEQ_LEN) v = *(const float4*)(kptr + (size_t)gk * 3072 + dq * 4);
            *(float4*)&KVs[row * LDSA + dq * 4] = v;
        }
        __syncthreads();

        float s[4][4];
        #pragma unroll
        for (int i = 0; i < 4; i++)
            #pragma unroll
            for (int j = 0; j < 4; j++) s[i][j] = 0.f;

        #pragma unroll
        for (int d4 = 0; d4 < 16; d4++) {
            float4 qv[4], kv[4];
            #pragma unroll
            for (int i = 0; i < 4; i++)
                qv[i] = *(const float4*)&Qs[(rg + 16 * i) * LDSA + d4 * 4];
            #pragma unroll
            for (int j = 0; j < 4; j++)
                kv[j] = *(const float4*)&KVs[(c + 16 * j) * LDSA + d4 * 4];
            #pragma unroll
            for (int i = 0; i < 4; i++)
                #pragma unroll
                for (int j = 0; j < 4; j++) {
                    s[i][j] = fmaf(qv[i].x, kv[j].x, s[i][j]);
                    s[i][j] = fmaf(qv[i].y, kv[j].y, s[i][j]);
                    s[i][j] = fmaf(qv[i].z, kv[j].z, s[i][j]);
                    s[i][j] = fmaf(qv[i].w, kv[j].w, s[i][j]);
                }
        }

        #pragma unroll
        for (int i = 0; i < 4; i++) {
            const int gq = qBase + rg + 16 * i;
            #pragma unroll
            for (int j = 0; j < 4; j++) {
                const int gk = kBase + c + 16 * j;
                float sv = s[i][j] * SCALE_F;
                if (gk >= SEQ_LEN) {
                    sv = -1e30f;
                } else if (gq >= NPATCH && gq < SEQ_LEN && gk < NPATCH) {
                    const float mv =
                        mask[((size_t)b * NQUERY + (gq - NPATCH)) * NPATCH + gk];
                    if (!(mv > 0.5f)) sv = -1e9f;
                }
                s[i][j] = sv;
            }
        }

        #pragma unroll
        for (int i = 0; i < 4; i++) {
            float mx = fmaxf(fmaxf(s[i][0], s[i][1]), fmaxf(s[i][2], s[i][3]));
            #pragma unroll
            for (int off = 1; off < 16; off <<= 1)
                mx = fmaxf(mx, __shfl_xor_sync(0xffffffffu, mx, off));
            const float nm    = fmaxf(m[i], mx);
            const float alpha = __expf(m[i] - nm);
            m[i] = nm;
            float rs = 0.f;
            #pragma unroll
            for (int j = 0; j < 4; j++) {
                const float p = __expf(s[i][j] - nm);
                rs += p;
                Ps[(rg + 16 * i) * LDSA + c + 16 * j] = p;
            }
            #pragma unroll
            for (int off = 1; off < 16; off <<= 1)
                rs += __shfl_xor_sync(0xffffffffu, rs, off);
            l[i] = l[i] * alpha + rs;
            o[i].x *= alpha; o[i].y *= alpha; o[i].z *= alpha; o[i].w *= alpha;
        }
        __syncthreads();

        for (int slot = t; slot < 64 * 16; slot += 256) {
            const int row = slot >> 4, dq = slot & 15;
            const int gk = kBase + row;
            float4 v = make_float4(0.f, 0.f, 0.f, 0.f);
            if (gk < SEQ_LEN) v = *(const float4*)(vptr + (size_t)gk * 3072 + dq * 4);
            *(float4*)&KVs[row * LDSA + dq * 4] = v;
        }
        __syncthreads();

        #pragma unroll 4
        for (int k = 0; k < 64; k++) {
            const float4 vv = *(const float4*)&KVs[k * LDSA + c * 4];
            #pragma unroll
            for (int i = 0; i < 4; i++) {
                const float p = Ps[(rg + 16 * i) * LDSA + k];
                o[i].x = fmaf(p, vv.x, o[i].x);
                o[i].y = fmaf(p, vv.y, o[i].y);
                o[i].z = fmaf(p, vv.z, o[i].z);
                o[i].w = fmaf(p, vv.w, o[i].w);
            }
        }
        __syncthreads();
    }

    #pragma unroll
    for (int i = 0; i < 4; i++) {
        const int gq = qBase + rg + 16 * i;
        if (gq < SEQ_LEN) {
            const float inv = 1.0f / l[i];
            float4 r = make_float4(o[i].x * inv, o[i].y * inv,
                                   o[i].z * inv, o[i].w * inv);
            *(float4*)(out + ((size_t)(b * SEQ_LEN + gq)) * EMBED
                           + h * HEADDIM + c * 4) = r;
        }
    }
}

// ---------------------------------------------------------------------------
// Launch
// ---------------------------------------------------------------------------
extern "C" void kernel_launch(void* const* d_in, const int* in_sizes, int n_in,
                              void* d_out, int out_size)
{
    const float* x      = (const float*)d_in[0];
    const float* mask   = (const float*)d_in[1];
    const float* qkv_w  = (const float*)d_in[2];
    const float* proj_w = (const float*)d_in[3];
    const float* proj_b = (const float*)d_in[4];
    const float* ln1_g  = (const float*)d_in[5];
    const float* ln1_b  = (const float*)d_in[6];
    const float* ln2_g  = (const float*)d_in[7];
    const float* ln2_b  = (const float*)d_in[8];
    const float* fc1_w  = (const float*)d_in[9];
    const float* fc1_b  = (const float*)d_in[10];
    const float* fc2_w  = (const float*)d_in[11];
    const float* fc2_b  = (const float*)d_in[12];
    float* out = (float*)d_out;

    float *p_xn, *p_qkv, *p_attn, *p_x1, *p_mid;
    cudaGetSymbolAddress((void**)&p_xn,   g_xn);
    cudaGetSymbolAddress((void**)&p_qkv,  g_qkv);
    cudaGetSymbolAddress((void**)&p_attn, g_attn);
    cudaGetSymbolAddress((void**)&p_x1,   g_x1);
    cudaGetSymbolAddress((void**)&p_mid,  g_mid);

    cudaFuncSetAttribute(attn_kernel,
                         cudaFuncAttributeMaxDynamicSharedMemorySize, ATTN_SMEM);

    const int M = TOKENS;                        // 8992
    const dim3 blk(256);
    const int mblk = (M + TBM - 1) / TBM;        // 71

    // 1) LN1
    ln_kernel<<<M, blk>>>(x, ln1_g, ln1_b, p_xn);
    // 2) qkv = xn @ qkv_w
    gemm_tf32_kernel<<<dim3(3 * EMBED / TBN, mblk), blk>>>(
        p_xn, qkv_w, nullptr, nullptr, p_qkv, M, 3 * EMBED, EMBED, 0);
    // 3) attention
    attn_kernel<<<dim3(18, BATCH * NHEADS), blk, ATTN_SMEM>>>(p_qkv, mask, p_attn);
    // 4) x1 = attn @ proj_w + proj_b + x
    gemm_tf32_kernel<<<dim3(EMBED / TBN, mblk), blk>>>(
        p_attn, proj_w, proj_b, x, p_x1, M, EMBED, EMBED, 0);
    // 5) LN2 (reuse xn buffer)
    ln_kernel<<<M, blk>>>(p_x1, ln2_g, ln2_b, p_xn);
    // 6) mid = gelu(xn @ fc1_w + fc1_b)
    gemm_tf32_kernel<<<dim3(MLP_HID / TBN, mblk), blk>>>(
        p_xn, fc1_w, fc1_b, nullptr, p_mid, M, MLP_HID, EMBED, 1);
    // 7) out = mid @ fc2_w + fc2_b + x1
    gemm_tf32_kernel<<<dim3(EMBED / TBN, mblk), blk>>>(
        p_mid, fc2_w, fc2_b, p_x1, out, M, EMBED, MLP_HID, 0);
}

// round 5
// speedup vs baseline: 2.2025x; 1.0051x over previous
#include <cuda_runtime.h>
#include <cuda_bf16.h>
#include <cstdint>
#include <cstddef>

// ---------------------------------------------------------------------------
// Problem constants
// ---------------------------------------------------------------------------
#define BATCH      8
#define SEQ_LEN    1124
#define EMBED      1024
#define NHEADS     16
#define HEADDIM    64
#define MLP_HID    4096
#define NPATCH     1024
#define NQUERY     100
#define TOKENS     (BATCH * SEQ_LEN)          // 8992
#define SCALE_F    0.125f                     // 64^-0.5
#define LN_EPS     1e-6f

// ---------------------------------------------------------------------------
// Scratch (static __device__ arrays; no allocation allowed)
// ---------------------------------------------------------------------------
__device__ float g_xn  [(size_t)TOKENS * EMBED];    // LN1 out, reused as LN2 out
__device__ float g_qkv [(size_t)TOKENS * 3 * EMBED];
__device__ float g_attn[(size_t)TOKENS * EMBED];
__device__ float g_x1  [(size_t)TOKENS * EMBED];    // x + attn proj (residual 1)
__device__ float g_mid [(size_t)TOKENS * MLP_HID];  // gelu(fc1)

// ---------------------------------------------------------------------------
// PTX helpers
// ---------------------------------------------------------------------------
__device__ __forceinline__ uint32_t f2tf32(float f) {
    uint32_t u;
    asm("cvt.rna.tf32.f32 %0, %1;" : "=r"(u) : "f"(f));
    return u;
}

__device__ __forceinline__ void mma_tf32(float* d, const uint32_t* a,
                                         const uint32_t* b) {
    asm volatile(
        "mma.sync.aligned.m16n8k8.row.col.f32.tf32.tf32.f32 "
        "{%0,%1,%2,%3}, {%4,%5,%6,%7}, {%8,%9}, {%0,%1,%2,%3};\n"
        : "+f"(d[0]), "+f"(d[1]), "+f"(d[2]), "+f"(d[3])
        : "r"(a[0]), "r"(a[1]), "r"(a[2]), "r"(a[3]),
          "r"(b[0]), "r"(b[1]));
}

// ---------------------------------------------------------------------------
// LayerNorm: one block per token row (1024 elems, 256 threads x float4)
// ---------------------------------------------------------------------------
__global__ void __launch_bounds__(256)
ln_kernel(const float* __restrict__ x, const float* __restrict__ g,
          const float* __restrict__ b, float* __restrict__ y)
{
    const int row = blockIdx.x;
    const int t   = threadIdx.x;
    const float* xr = x + (size_t)row * EMBED;

    float4 v = *(const float4*)(xr + t * 4);
    float s  = v.x + v.y + v.z + v.w;
    float sq = v.x*v.x + v.y*v.y + v.z*v.z + v.w*v.w;

    #pragma unroll
    for (int off = 16; off > 0; off >>= 1) {
        s  += __shfl_xor_sync(0xffffffffu, s,  off);
        sq += __shfl_xor_sync(0xffffffffu, sq, off);
    }
    __shared__ float red_s[8], red_q[8];
    const int wid = t >> 5, lane = t & 31;
    if (lane == 0) { red_s[wid] = s; red_q[wid] = sq; }
    __syncthreads();
    float ts = 0.f, tq = 0.f;
    #pragma unroll
    for (int w = 0; w < 8; w++) { ts += red_s[w]; tq += red_q[w]; }

    const float mean = ts * (1.0f / EMBED);
    const float var  = tq * (1.0f / EMBED) - mean * mean;
    const float inv  = rsqrtf(var + LN_EPS);

    float4 gg = *(const float4*)(g + t * 4);
    float4 bb = *(const float4*)(b + t * 4);
    float4 o;
    o.x = (v.x - mean) * inv * gg.x + bb.x;
    o.y = (v.y - mean) * inv * gg.y + bb.y;
    o.z = (v.z - mean) * inv * gg.z + bb.z;
    o.w = (v.w - mean) * inv * gg.w + bb.w;
    *(float4*)(y + (size_t)row * EMBED + t * 4) = o;
}

// ---------------------------------------------------------------------------
// TF32 tensor-core GEMM: C[M,N] = A[M,K] @ B[K,N] (+bias)(+GELU)(+residual)
// 128x128x32 CTA tile, 256 threads (8 warps, 4 warpM x 2 warpN), warp 32x64.
// Fragment-major tf32 smem: convert once at staging, inner loop = LDS.128
// only (conflict-free), double-buffered, one barrier per K-tile.
// N % 128 == 0, K % 32 == 0; M ragged (predicated, addresses clamped).
// ---------------------------------------------------------------------------
#define TBM 128
#define TBN 128
#define TBK 32
#define LANE_A 36                         // 32 frag words + 4 pad (16B aligned)
#define LANE_B 68                         // 64 frag words + 4 pad
#define AFRAG_WORDS (4 * 32 * LANE_A)     // 4608 words (= A tile, no dup)
#define BFRAG_WORDS (2 * 32 * LANE_B)     // 4352 words (= B tile, no dup)
#define BUF_WORDS   (AFRAG_WORDS + BFRAG_WORDS)   // 8960
#define GEMM_SMEM   (2 * BUF_WORDS * 4)           // 71680 B

__global__ void __launch_bounds__(256)
gemm_tf32_kernel(const float* __restrict__ A, const float* __restrict__ B,
                 const float* __restrict__ bias, const float* __restrict__ res,
                 float* __restrict__ C, int M, int N, int K, int doGelu)
{
    extern __shared__ uint32_t smem_u[];

    const int t     = threadIdx.x;
    const int wid   = t >> 5;
    const int lane  = t & 31;
    const int warpM = wid & 3;     // 4 warps along M (32 rows each)
    const int warpN = wid >> 2;    // 2 warps along N (64 cols each)
    const int g     = lane >> 2;   // 0..7
    const int tg    = lane & 3;    // 0..3
    const int gRow0 = blockIdx.y * TBM;
    const int gCol0 = blockIdx.x * TBN;

    // global load mapping
    const int a_r  = t >> 3;            // 0..31 (A rows, +32 per i)
    const int a_kq = t & 7;             // k-quad 0..7
    const int b_kr = t >> 5;            // 0..7 (B k-rows, +8 per i)
    const int b_nq = t & 31;            // n-quad 0..31

    // precomputed staging destinations
    const int st_ks    = a_kq >> 1;
    const int st_khalf = a_kq & 1;
    // B: warpN/ni/g0 independent of u within a float4
    const int stb_warpN = b_nq >> 4;
    const int stb_ni    = (b_nq & 15) >> 1;
    const int stb_g0    = 4 * (b_nq & 1);
    const int stb_khalf = b_kr >> 2;
    const int stb_tg    = b_kr & 3;

    float acc[2][8][4];
    #pragma unroll
    for (int mi = 0; mi < 2; mi++)
        #pragma unroll
        for (int ni = 0; ni < 8; ni++)
            #pragma unroll
            for (int u = 0; u < 4; u++) acc[mi][ni][u] = 0.f;

    float4 ra[4], rb[4];
    auto fetchTile = [&](int kt) {
        const int k0 = kt * TBK;
        #pragma unroll
        for (int i = 0; i < 4; i++) {
            const int gr  = gRow0 + a_r + i * 32;
            const int grc = gr < M ? gr : (M - 1);   // clamped, in-bounds
            ra[i] = *(const float4*)(A + (size_t)grc * K + k0 + a_kq * 4);
        }
        #pragma unroll
        for (int i = 0; i < 4; i++) {
            const int r = b_kr + i * 8;
            rb[i] = *(const float4*)(B + (size_t)(k0 + r) * N + gCol0 + b_nq * 4);
        }
    };

    auto stageTile = [&](int buf) {
        uint32_t* Af = smem_u + buf * BUF_WORDS;
        uint32_t* Bf = Af + AFRAG_WORDS;
        // A: value (row r, k) -> Af[warpM(r)*1152 + (g*4+tg)*LANE_A + idx]
        //    idx = ks*8 + mi*4 + (half + 2*khalf),  tg = k%4
        #pragma unroll
        for (int i = 0; i < 4; i++) {
            const int r   = a_r + i * 32;
            const int wM  = r >> 5;
            const int rr  = r & 31;
            const int mi  = rr >> 4;
            const int hf  = (rr >> 3) & 1;
            const int gg  = rr & 7;
            const int idx = st_ks * 8 + mi * 4 + hf + 2 * st_khalf;
            uint32_t* p = Af + wM * (32 * LANE_A) + gg * 4 * LANE_A + idx;
            p[0 * LANE_A] = f2tf32(ra[i].x);
            p[1 * LANE_A] = f2tf32(ra[i].y);
            p[2 * LANE_A] = f2tf32(ra[i].z);
            p[3 * LANE_A] = f2tf32(ra[i].w);
        }
        // B: value (k, n) -> Bf[warpN(n)*2176 + ((g0+u)*4+tg)*LANE_B + idx]
        //    idx = ks*16 + ni*2 + khalf
        #pragma unroll
        for (int i = 0; i < 4; i++) {
            const int idx = i * 16 + stb_ni * 2 + stb_khalf;
            uint32_t* p = Bf + stb_warpN * (32 * LANE_B)
                             + (stb_g0 * 4 + stb_tg) * LANE_B + idx;
            p[0 * 4 * LANE_B] = f2tf32(rb[i].x);
            p[1 * 4 * LANE_B] = f2tf32(rb[i].y);
            p[2 * 4 * LANE_B] = f2tf32(rb[i].z);
            p[3 * 4 * LANE_B] = f2tf32(rb[i].w);
        }
    };

    auto computeTile = [&](int buf) {
        const uint32_t* Afl = smem_u + buf * BUF_WORDS
                              + warpM * (32 * LANE_A) + lane * LANE_A;
        const uint32_t* Bfl = smem_u + buf * BUF_WORDS + AFRAG_WORDS
                              + warpN * (32 * LANE_B) + lane * LANE_B;
        #pragma unroll
        for (int ks = 0; ks < 4; ks++) {
            uint4 a0 = *(const uint4*)(Afl + ks * 8);
            uint4 a1 = *(const uint4*)(Afl + ks * 8 + 4);
            uint4 w0 = *(const uint4*)(Bfl + ks * 16);
            uint4 w1 = *(const uint4*)(Bfl + ks * 16 + 4);
            uint4 w2 = *(const uint4*)(Bfl + ks * 16 + 8);
            uint4 w3 = *(const uint4*)(Bfl + ks * 16 + 12);
            uint32_t af0[4] = {a0.x, a0.y, a0.z, a0.w};
            uint32_t af1[4] = {a1.x, a1.y, a1.z, a1.w};
            uint32_t bw[16] = {w0.x, w0.y, w0.z, w0.w,
                               w1.x, w1.y, w1.z, w1.w,
                               w2.x, w2.y, w2.z, w2.w,
                               w3.x, w3.y, w3.z, w3.w};
            #pragma unroll
            for (int ni = 0; ni < 8; ni++) {
                mma_tf32(acc[0][ni], af0, &bw[2 * ni]);
                mma_tf32(acc[1][ni], af1, &bw[2 * ni]);
            }
        }
    };

    const int nk = K / TBK;
    fetchTile(0);
    stageTile(0);
    __syncthreads();

    for (int kt = 0; kt < nk; kt++) {
        const int buf = kt & 1;
        if (kt + 1 < nk) fetchTile(kt + 1);   // global -> regs, overlaps compute
        computeTile(buf);
        if (kt + 1 < nk) stageTile(buf ^ 1);  // regs -> other buffer
        __syncthreads();
    }

    // epilogue: frag c0:(g,2tg) c1:(g,2tg+1) c2:(g+8,2tg) c3:(g+8,2tg+1)
    #pragma unroll
    for (int mi = 0; mi < 2; mi++) {
        #pragma unroll
        for (int half = 0; half < 2; half++) {
            const int r = gRow0 + warpM * 32 + mi * 16 + g + half * 8;
            if (r >= M) continue;
            #pragma unroll
            for (int ni = 0; ni < 8; ni++) {
                const int col = gCol0 + warpN * 64 + ni * 8 + tg * 2;
                float v0 = acc[mi][ni][half * 2 + 0];
                float v1 = acc[mi][ni][half * 2 + 1];
                if (bias) { v0 += bias[col]; v1 += bias[col + 1]; }
                if (doGelu) {
                    v0 = 0.5f * v0 * (1.0f + erff(v0 * 0.70710678118654752f));
                    v1 = 0.5f * v1 * (1.0f + erff(v1 * 0.70710678118654752f));
                }
                if (res) {
                    const float2 rv = *(const float2*)(res + (size_t)r * N + col);
                    v0 += rv.x; v1 += rv.y;
                }
                *(float2*)(C + (size_t)r * N + col) = make_float2(v0, v1);
            }
        }
    }
}

// ---------------------------------------------------------------------------
// Flash-style attention, fp32. One block = (one (b,h), 64 q-rows).
// 256 threads: t = rg*16 + c;  rg in [0,16) -> rows {rg, rg+16, rg+32, rg+48}
//                               c  in [0,16) -> keys {c, c+16, c+32, c+48} (scores)
//                                              dims {4c..4c+3}            (PV / out)
// ---------------------------------------------------------------------------
#define LDSA 68
#define ATTN_SMEM (3 * 64 * LDSA * 4)

__global__ void __launch_bounds__(256)
attn_kernel(const float* __restrict__ qkv, const float* __restrict__ mask,
            float* __restrict__ out)
{
    extern __shared__ float sm[];
    float* Qs  = sm;
    float* KVs = sm + 64 * LDSA;
    float* Ps  = sm + 2 * 64 * LDSA;

    const int t  = threadIdx.x;
    const int qt = blockIdx.x;            // 0..17
    const int bh = blockIdx.y;            // 0..127
    const int b  = bh >> 4;
    const int h  = bh & 15;
    const int qBase = qt * 64;

    const float* qptr = qkv + (size_t)b * SEQ_LEN * 3072 + h * HEADDIM;
    const float* kptr = qptr + EMBED;
    const float* vptr = qptr + 2 * EMBED;

    for (int slot = t; slot < 64 * 16; slot += 256) {
        const int row = slot >> 4, dq = slot & 15;
        const int gq = qBase + row;
        float4 v = make_float4(0.f, 0.f, 0.f, 0.f);
        if (gq < SEQ_LEN) v = *(const float4*)(qptr + (size_t)gq * 3072 + dq * 4);
        *(float4*)&Qs[row * LDSA + dq * 4] = v;
    }

    const int rg = t >> 4;
    const int c  = t & 15;

    float m[4], l[4];
    float4 o[4];
    #pragma unroll
    for (int i = 0; i < 4; i++) {
        m[i] = -1e30f; l[i] = 0.f; o[i] = make_float4(0.f, 0.f, 0.f, 0.f);
    }
    __syncthreads();

    const int nkt = (SEQ_LEN + 63) / 64;   // 18
    for (int kt = 0; kt < nkt; kt++) {
        const int kBase = kt * 64;

        for (int slot = t; slot < 64 * 16; slot += 256) {
            const int row = slot >> 4, dq = slot & 15;
            const int gk = kBase + row;
            float4 v = make_float4(0.f, 0.f, 0.f, 0.f);
            if (gk < SEQ_LEN) v = *(const float4*)(kptr + (size_t)gk * 3072 + dq * 4);
            *(float4*)&KVs[row * LDSA + dq * 4] = v;
        }
        __syncthreads();

        float s[4][4];
        #pragma unroll
        for (int i = 0; i < 4; i++)
            #pragma unroll
            for (int j = 0; j < 4; j++) s[i][j] = 0.f;

        #pragma unroll
        for (int d4 = 0; d4 < 16; d4++) {
            float4 qv[4], kv[4];
            #pragma unroll
            for (int i = 0; i < 4; i++)
                qv[i] = *(const float4*)&Qs[(rg + 16 * i) * LDSA + d4 * 4];
            #pragma unroll
            for (int j = 0; j < 4; j++)
                kv[j] = *(const float4*)&KVs[(c + 16 * j) * LDSA + d4 * 4];
            #pragma unroll
            for (int i = 0; i < 4; i++)
                #pragma unroll
                for (int j = 0; j < 4; j++) {
                    s[i][j] = fmaf(qv[i].x, kv[j].x, s[i][j]);
                    s[i][j] = fmaf(qv[i].y, kv[j].y, s[i][j]);
                    s[i][j] = fmaf(qv[i].z, kv[j].z, s[i][j]);
                    s[i][j] = fmaf(qv[i].w, kv[j].w, s[i][j]);
                }
        }

        #pragma unroll
        for (int i = 0; i < 4; i++) {
            const int gq = qBase + rg + 16 * i;
            #pragma unroll
            for (int j = 0; j < 4; j++) {
                const int gk = kBase + c + 16 * j;
                float sv = s[i][j] * SCALE_F;
                if (gk >= SEQ_LEN) {
                    sv = -1e30f;
                } else if (gq >= NPATCH && gq < SEQ_LEN && gk < NPATCH) {
                    const float mv =
                        mask[((size_t)b * NQUERY + (gq - NPATCH)) * NPATCH + gk];
                    if (!(mv > 0.5f)) sv = -1e9f;
                }
                s[i][j] = sv;
            }
        }

        #pragma unroll
        for (int i = 0; i < 4; i++) {
            float mx = fmaxf(fmaxf(s[i][0], s[i][1]), fmaxf(s[i][2], s[i][3]));
            #pragma unroll
            for (int off = 1; off < 16; off <<= 1)
                mx = fmaxf(mx, __shfl_xor_sync(0xffffffffu, mx, off));
            const float nm    = fmaxf(m[i], mx);
            const float alpha = __expf(m[i] - nm);
            m[i] = nm;
            float rs = 0.f;
            #pragma unroll
            for (int j = 0; j < 4; j++) {
                const float p = __expf(s[i][j] - nm);
                rs += p;
                Ps[(rg + 16 * i) * LDSA + c + 16 * j] = p;
            }
            #pragma unroll
            for (int off = 1; off < 16; off <<= 1)
                rs += __shfl_xor_sync(0xffffffffu, rs, off);
            l[i] = l[i] * alpha + rs;
            o[i].x *= alpha; o[i].y *= alpha; o[i].z *= alpha; o[i].w *= alpha;
        }
        __syncthreads();

        for (int slot = t; slot < 64 * 16; slot += 256) {
            const int row = slot >> 4, dq = slot & 15;
            const int gk = kBase + row;
            float4 v = make_float4(0.f, 0.f, 0.f, 0.f);
            if (gk < SEQ_LEN) v = *(const float4*)(vptr + (size_t)gk * 3072 + dq * 4);
            *(float4*)&KVs[row * LDSA + dq * 4] = v;
        }
        __syncthreads();

        #pragma unroll 4
        for (int k = 0; k < 64; k++) {
            const float4 vv = *(const float4*)&KVs[k * LDSA + c * 4];
            #pragma unroll
            for (int i = 0; i < 4; i++) {
                const float p = Ps[(rg + 16 * i) * LDSA + k];
                o[i].x = fmaf(p, vv.x, o[i].x);
                o[i].y = fmaf(p, vv.y, o[i].y);
                o[i].z = fmaf(p, vv.z, o[i].z);
                o[i].w = fmaf(p, vv.w, o[i].w);
            }
        }
        __syncthreads();
    }

    #pragma unroll
    for (int i = 0; i < 4; i++) {
        const int gq = qBase + rg + 16 * i;
        if (gq < SEQ_LEN) {
            const float inv = 1.0f / l[i];
            float4 r = make_float4(o[i].x * inv, o[i].y * inv,
                                   o[i].z * inv, o[i].w * inv);
            *(float4*)(out + ((size_t)(b * SEQ_LEN + gq)) * EMBED
                           + h * HEADDIM + c * 4) = r;
        }
    }
}

// ---------------------------------------------------------------------------
// Launch
// ---------------------------------------------------------------------------
extern "C" void kernel_launch(void* const* d_in, const int* in_sizes, int n_in,
                              void* d_out, int out_size)
{
    const float* x      = (const float*)d_in[0];
    const float* mask   = (const float*)d_in[1];
    const float* qkv_w  = (const float*)d_in[2];
    const float* proj_w = (const float*)d_in[3];
    const float* proj_b = (const float*)d_in[4];
    const float* ln1_g  = (const float*)d_in[5];
    const float* ln1_b  = (const float*)d_in[6];
    const float* ln2_g  = (const float*)d_in[7];
    const float* ln2_b  = (const float*)d_in[8];
    const float* fc1_w  = (const float*)d_in[9];
    const float* fc1_b  = (const float*)d_in[10];
    const float* fc2_w  = (const float*)d_in[11];
    const float* fc2_b  = (const float*)d_in[12];
    float* out = (float*)d_out;

    float *p_xn, *p_qkv, *p_attn, *p_x1, *p_mid;
    cudaGetSymbolAddress((void**)&p_xn,   g_xn);
    cudaGetSymbolAddress((void**)&p_qkv,  g_qkv);
    cudaGetSymbolAddress((void**)&p_attn, g_attn);
    cudaGetSymbolAddress((void**)&p_x1,   g_x1);
    cudaGetSymbolAddress((void**)&p_mid,  g_mid);

    cudaFuncSetAttribute(attn_kernel,
                         cudaFuncAttributeMaxDynamicSharedMemorySize, ATTN_SMEM);
    cudaFuncSetAttribute(gemm_tf32_kernel,
                         cudaFuncAttributeMaxDynamicSharedMemorySize, GEMM_SMEM);

    const int M = TOKENS;                        // 8992
    const dim3 blk(256);
    const int mblk = (M + TBM - 1) / TBM;        // 71

    // 1) LN1
    ln_kernel<<<M, blk>>>(x, ln1_g, ln1_b, p_xn);
    // 2) qkv = xn @ qkv_w
    gemm_tf32_kernel<<<dim3(3 * EMBED / TBN, mblk), blk, GEMM_SMEM>>>(
        p_xn, qkv_w, nullptr, nullptr, p_qkv, M, 3 * EMBED, EMBED, 0);
    // 3) attention
    attn_kernel<<<dim3(18, BATCH * NHEADS), blk, ATTN_SMEM>>>(p_qkv, mask, p_attn);
    // 4) x1 = attn @ proj_w + proj_b + x
    gemm_tf32_kernel<<<dim3(EMBED / TBN, mblk), blk, GEMM_SMEM>>>(
        p_attn, proj_w, proj_b, x, p_x1, M, EMBED, EMBED, 0);
    // 5) LN2 (reuse xn buffer)
    ln_kernel<<<M, blk>>>(p_x1, ln2_g, ln2_b, p_xn);
    // 6) mid = gelu(xn @ fc1_w + fc1_b)
    gemm_tf32_kernel<<<dim3(MLP_HID / TBN, mblk), blk, GEMM_SMEM>>>(
        p_xn, fc1_w, fc1_b, nullptr, p_mid, M, MLP_HID, EMBED, 1);
    // 7) out = mid @ fc2_w + fc2_b + x1
    gemm_tf32_kernel<<<dim3(EMBED / TBN, mblk), blk, GEMM_SMEM>>>(
        p_mid, fc2_w, fc2_b, p_x1, out, M, EMBED, MLP_HID, 0);
}